// round 14
// baseline (speedup 1.0000x reference)
#include <cuda_runtime.h>
#include <cuda_fp16.h>
#include <cstdint>

// ---------------- problem constants ----------------
#define DIM_B 4
#define DIM_N 1024
#define DIM_D 512
#define DIM_F 16
#define DIM_O 64
#define DIM_V 64
// out[b,n,f,o] = sum_d (x[b,n,d] + bias[idx[b,f],d]) * W[idx[b,f]][d,o]
//             = (X[b] @ Wcat[b])[n, f*64+o] + cbias[b,f,o]
// X, W pre-converted to fp16 (same 10-bit mantissa as tf32); accumulate fp32.

// ---------------- helpers ----------------
__device__ __forceinline__ uint32_t smem_u32(const void* p) {
    uint32_t a;
    asm("{ .reg .u64 t; cvta.to.shared.u64 t, %1; cvt.u32.u64 %0, t; }"
        : "=r"(a) : "l"(p));
    return a;
}

__device__ __forceinline__ void cp_async16(uint32_t smem_dst, const void* gptr) {
    asm volatile("cp.async.cg.shared.global [%0], [%1], 16;"
                 :: "r"(smem_dst), "l"(gptr) : "memory");
}

__device__ __forceinline__ void ldmatrix_x4(uint32_t& r0, uint32_t& r1,
                                            uint32_t& r2, uint32_t& r3,
                                            uint32_t addr) {
    asm volatile("ldmatrix.sync.aligned.m8n8.x4.shared.b16 {%0,%1,%2,%3}, [%4];"
                 : "=r"(r0), "=r"(r1), "=r"(r2), "=r"(r3) : "r"(addr));
}

__device__ __forceinline__ void ldmatrix_x4_trans(uint32_t& r0, uint32_t& r1,
                                                  uint32_t& r2, uint32_t& r3,
                                                  uint32_t addr) {
    asm volatile("ldmatrix.sync.aligned.m8n8.x4.trans.shared.b16 {%0,%1,%2,%3}, [%4];"
                 : "=r"(r0), "=r"(r1), "=r"(r2), "=r"(r3) : "r"(addr));
}

__device__ __forceinline__ void mma_f16(float& c0, float& c1, float& c2, float& c3,
                                        uint32_t a0, uint32_t a1, uint32_t a2, uint32_t a3,
                                        uint32_t b0, uint32_t b1) {
    asm volatile(
        "mma.sync.aligned.m16n8k16.row.col.f32.f16.f16.f32 "
        "{%0,%1,%2,%3}, {%4,%5,%6,%7}, {%8,%9}, {%0,%1,%2,%3};"
        : "+f"(c0), "+f"(c1), "+f"(c2), "+f"(c3)
        : "r"(a0), "r"(a1), "r"(a2), "r"(a3), "r"(b0), "r"(b1));
}

// ---------------- device scratch (no allocs allowed) ----------------
__device__ __half g_xh[DIM_B * DIM_N * DIM_D];         // 4 MB, fp16 x
__device__ __half g_wh[DIM_V * DIM_D * DIM_O];         // 4 MB, fp16 W (native [v][d][o])
__device__ float  g_cbias[DIM_B * DIM_F * DIM_O];      // bias @ W, full fp32

static constexpr int X_ELEMS = DIM_B * DIM_N * DIM_D;  // 2M
static constexpr int W_ELEMS = DIM_V * DIM_D * DIM_O;  // 2M
static constexpr int XBLK = X_ELEMS / (256 * 8);       // 1024
static constexpr int WBLK = W_ELEMS / (256 * 8);       // 1024  (16 blocks per v)

// ---------------- fused prep (R7 form, EPT=8 — measured best) ----------------
__global__ void __launch_bounds__(256) prep_kernel(
    const float* __restrict__ x,
    const int* __restrict__ idx,
    const float* __restrict__ bias_tab,
    const float* __restrict__ w_tab)
{
    const int bid = blockIdx.x;
    const int tid = threadIdx.x;

    if (bid < XBLK + WBLK) {
        const float* src;
        __half* dst;
        size_t i;
        if (bid < XBLK) {
            i = ((size_t)bid * 256 + tid) * 8;
            src = x; dst = g_xh;
        } else {
            // 16 blocks per vocab entry; skip entries not referenced by idx
            int v = (bid - XBLK) >> 4;
            int used = __syncthreads_or(tid < DIM_B * DIM_F && idx[tid] == v);
            if (!used) return;
            i = ((size_t)(bid - XBLK) * 256 + tid) * 8;
            src = w_tab; dst = g_wh;
        }
        float4 v0 = *reinterpret_cast<const float4*>(src + i);
        float4 v1 = *reinterpret_cast<const float4*>(src + i + 4);
        __half2 h[4];
        h[0] = __float22half2_rn(make_float2(v0.x, v0.y));
        h[1] = __float22half2_rn(make_float2(v0.z, v0.w));
        h[2] = __float22half2_rn(make_float2(v1.x, v1.y));
        h[3] = __float22half2_rn(make_float2(v1.z, v1.w));
        *reinterpret_cast<uint4*>(dst + i) = *reinterpret_cast<uint4*>(h);
    } else {
        // ---- bias part: cbias[p][o] = sum_d bias[v][d] * W[v][d][o], fp32
        int p = bid - XBLK - WBLK;      // 0..63
        int v = idx[p];
        int o = tid & 63;
        int slice = tid >> 6;           // 0..3, 128 d's each
        const float* bptr = bias_tab + (size_t)v * DIM_D;
        const float* wptr = w_tab + (size_t)v * DIM_D * DIM_O + o;
        float acc = 0.f;
        int d0 = slice * 128;
        #pragma unroll 8
        for (int d = d0; d < d0 + 128; ++d)
            acc += bptr[d] * wptr[(size_t)d * DIM_O];
        __shared__ float red[256];
        red[tid] = acc;
        __syncthreads();
        if (slice == 0)
            g_cbias[p * DIM_O + o] = red[o] + red[o + 64] + red[o + 128] + red[o + 192];
    }
}

// ---------------- main GEMM: fp16 m16n8k16, 32 warps/SM (occ 2) --------------
// CTA tile: M=128, N=128 (2 f's x 64 o), K=512 in chunks of KC=64 halves.
// 512 threads, 16 warps as 4(m) x 4(n): warp tile 32 x 32 (~64 regs/thread).
// Grid = 8 x 8 x 4 = 256 CTAs, 2 CTAs/SM -> 32 warps/SM for latency hiding.
static constexpr int M_CTA = 128;
static constexpr int KC = 64;                    // halves per chunk (4 k16 steps)
static constexpr int CHUNKS = DIM_D / KC;        // 8
static constexpr int STAGES = 3;

// A smem: [128 m][KC halves] rows of 128 B data, stride 36 words (9 quads, odd)
// B smem: [KC k][128 n] rows of 256 B data, stride 68 words (17 quads, odd)
// odd quad strides => ldmatrix 8-row phases hit distinct 16B banks.
static constexpr int A_RS = 36;                           // words
static constexpr int B_RS = 68;                           // words
static constexpr int A_BYTES  = M_CTA * A_RS * 4;         // 18432
static constexpr int B_BYTES  = KC * B_RS * 4;            // 17408
static constexpr int STAGE_BYTES = A_BYTES + B_BYTES;     // 35840
static constexpr int SMEM_TOTAL  = STAGES * STAGE_BYTES;  // 107520 (x2 CTAs = 215K)

__global__ void __launch_bounds__(512, 2) mm_kernel(
    const int* __restrict__ idx,
    float* __restrict__ out)
{
    extern __shared__ char smem[];
    const uint32_t smem_base = smem_u32(smem);

    const int tid  = threadIdx.x;
    const int wid  = tid >> 5;
    const int lane = tid & 31;
    const int grp  = lane >> 2;         // 0..7
    const int tg   = lane & 3;          // 0..3

    const int mtile  = blockIdx.x;      // 0..7  (128 rows each)
    const int ntile  = blockIdx.y;      // 0..7
    const int b      = blockIdx.z;      // 0..3
    const int f_base = ntile * 2;

    const int v0 = idx[b * DIM_F + f_base];
    const int v1 = idx[b * DIM_F + f_base + 1];

    const __half* xbase = g_xh + ((size_t)b * DIM_N + (size_t)mtile * M_CTA) * DIM_D;
    const __half* w0 = g_wh + (size_t)v0 * DIM_D * DIM_O;   // [d][o]
    const __half* w1 = g_wh + (size_t)v1 * DIM_D * DIM_O;

    // per chunk: A = 128 rows x 128 B = 1024 segs (2/thread)
    //            B = 64 k-rows x 256 B = 1024 segs (2/thread)
    auto load_stage = [&](int stage, int k0) {
        uint32_t abase = smem_base + stage * STAGE_BYTES;
        uint32_t bbase = abase + A_BYTES;
        #pragma unroll
        for (int i = 0; i < 2; ++i) {
            int seg = tid + 512 * i;
            int row = seg >> 3, c8 = seg & 7;        // 8 x 16B per A row
            cp_async16(abase + (row * A_RS + c8 * 4) * 4,
                       xbase + (size_t)row * DIM_D + k0 + c8 * 8);
        }
        #pragma unroll
        for (int i = 0; i < 2; ++i) {
            int seg = tid + 512 * i;
            int k = seg >> 4, c16 = seg & 15;        // 16 x 16B per B k-row
            const __half* wsrc = ((c16 < 8) ? w0 : w1)
                                 + (size_t)(k0 + k) * DIM_O + (c16 & 7) * 8;
            cp_async16(bbase + (k * B_RS + c16 * 4) * 4, wsrc);
        }
    };

    const int warp_m = (wid >> 2) * 32;  // 0..96
    const int warp_n = (wid & 3) * 32;   // 0..96

    // A x4 (non-trans): rows warp_m+mt*16+(lane&15), k-halfword (lane>>4)*8
    const uint32_t a_off0 = ((warp_m + (lane & 15)) * A_RS + (lane >> 4) * 4) * 4;
    // B x4 trans: k-row (lane>>3 & 1)*8 + (lane&7); n-half ntp*16 + (lane>>4)*8
    const uint32_t b_off0 = ((((lane >> 3) & 1) * 8 + (lane & 7)) * B_RS) * 4
                            + (warp_n + (lane >> 4) * 8) * 2;

    float acc[2][4][4];
    #pragma unroll
    for (int mt = 0; mt < 2; ++mt)
        #pragma unroll
        for (int nt = 0; nt < 4; ++nt)
            #pragma unroll
            for (int c = 0; c < 4; ++c) acc[mt][nt][c] = 0.f;

    // ---- prologue: prefetch 2 chunks
    load_stage(0, 0);
    asm volatile("cp.async.commit_group;" ::: "memory");
    load_stage(1, KC);
    asm volatile("cp.async.commit_group;" ::: "memory");

    int cs = 0, ls = 2;                  // compute stage, load stage
    for (int chunk = 0; chunk < CHUNKS; ++chunk) {
        asm volatile("cp.async.wait_group 1;" ::: "memory");  // chunk landed
        __syncthreads();
        if (chunk + 2 < CHUNKS) load_stage(ls, (chunk + 2) * KC);
        asm volatile("cp.async.commit_group;" ::: "memory");  // empty at tail OK

        const uint32_t a_st = smem_base + cs * STAGE_BYTES;
        const uint32_t b_st = a_st + A_BYTES;

        #pragma unroll
        for (int s = 0; s < KC / 16; ++s) {
            // B first (feeds all MMAs), then per-mt A LDSM + its 4 MMAs
            uint32_t bfr[4][2];
            #pragma unroll
            for (int ntp = 0; ntp < 2; ++ntp)
                ldmatrix_x4_trans(bfr[2 * ntp][0], bfr[2 * ntp][1],
                                  bfr[2 * ntp + 1][0], bfr[2 * ntp + 1][1],
                                  b_st + b_off0 + ntp * 32 + s * 16 * B_RS * 4);
            #pragma unroll
            for (int mt = 0; mt < 2; ++mt) {
                uint32_t afr[4];
                ldmatrix_x4(afr[0], afr[1], afr[2], afr[3],
                            a_st + a_off0 + mt * 16 * A_RS * 4 + s * 32);
                #pragma unroll
                for (int nt = 0; nt < 4; ++nt)
                    mma_f16(acc[mt][nt][0], acc[mt][nt][1], acc[mt][nt][2], acc[mt][nt][3],
                            afr[0], afr[1], afr[2], afr[3],
                            bfr[nt][0], bfr[nt][1]);
            }
        }
        cs = (cs == 2) ? 0 : cs + 1;
        ls = (ls == 2) ? 0 : ls + 1;
    }

    // ---- epilogue: add cbias, store float2 (c0/c1 at cols 2*tg, rows grp/+8)
    const float* cbp = g_cbias + (b * DIM_F + f_base) * DIM_O;
    float2 cb[4];
    #pragma unroll
    for (int nt = 0; nt < 4; ++nt)
        cb[nt] = *reinterpret_cast<const float2*>(cbp + warp_n + nt * 8 + 2 * tg);

    #pragma unroll
    for (int mt = 0; mt < 2; ++mt) {
        #pragma unroll
        for (int r2 = 0; r2 < 2; ++r2) {
            int m_global = mtile * M_CTA + warp_m + mt * 16 + grp + r2 * 8;
            float* rowp = out + (((size_t)b * DIM_N + m_global) * DIM_F + f_base) * DIM_O;
            #pragma unroll
            for (int nt = 0; nt < 4; ++nt) {
                float2 ov;
                ov.x = acc[mt][nt][r2 * 2 + 0] + cb[nt].x;
                ov.y = acc[mt][nt][r2 * 2 + 1] + cb[nt].y;
                *reinterpret_cast<float2*>(rowp + warp_n + nt * 8 + 2 * tg) = ov;
            }
        }
    }
}

// ---------------- launch ----------------
extern "C" void kernel_launch(void* const* d_in, const int* in_sizes, int n_in,
                              void* d_out, int out_size) {
    const float* x        = (const float*)d_in[0];   // [4,1024,512] f32
    const int*   idx      = (const int*)d_in[1];     // [4,16] i32
    const float* bias_tab = (const float*)d_in[2];   // [64,512] f32
    const float* w_tab    = (const float*)d_in[3];   // [64, 512*64] f32
    float* out = (float*)d_out;                      // [4,1024,16,64] f32

    static bool attr_set = false;
    if (!attr_set) {
        cudaFuncSetAttribute(mm_kernel,
                             cudaFuncAttributeMaxDynamicSharedMemorySize, SMEM_TOTAL);
        attr_set = true;
    }

    prep_kernel<<<XBLK + WBLK + DIM_B * DIM_F, 256>>>(x, idx, bias_tab, w_tab);

    dim3 grid(DIM_N / M_CTA, DIM_N / 128, DIM_B);    // (8, 8, 4) = 256 CTAs
    mm_kernel<<<grid, 512, SMEM_TOTAL>>>(idx, out);
}

// round 17
// speedup vs baseline: 1.1650x; 1.1650x over previous
#include <cuda_runtime.h>
#include <cuda_fp16.h>
#include <cstdint>

// ---------------- problem constants ----------------
#define DIM_B 4
#define DIM_N 1024
#define DIM_D 512
#define DIM_F 16
#define DIM_O 64
#define DIM_V 64
// out[b,n,f,o] = sum_d (x[b,n,d] + bias[idx[b,f],d]) * W[idx[b,f]][d,o]
//             = (X[b] @ Wcat[b])[n, f*64+o] + cbias[b,f,o]
// X, W pre-converted to fp16 (same 10-bit mantissa as tf32); accumulate fp32.

// ---------------- helpers ----------------
__device__ __forceinline__ uint32_t smem_u32(const void* p) {
    uint32_t a;
    asm("{ .reg .u64 t; cvta.to.shared.u64 t, %1; cvt.u32.u64 %0, t; }"
        : "=r"(a) : "l"(p));
    return a;
}

__device__ __forceinline__ void cp_async16(uint32_t smem_dst, const void* gptr) {
    asm volatile("cp.async.cg.shared.global [%0], [%1], 16;"
                 :: "r"(smem_dst), "l"(gptr) : "memory");
}

__device__ __forceinline__ void ldmatrix_x4(uint32_t& r0, uint32_t& r1,
                                            uint32_t& r2, uint32_t& r3,
                                            uint32_t addr) {
    asm volatile("ldmatrix.sync.aligned.m8n8.x4.shared.b16 {%0,%1,%2,%3}, [%4];"
                 : "=r"(r0), "=r"(r1), "=r"(r2), "=r"(r3) : "r"(addr));
}

__device__ __forceinline__ void ldmatrix_x4_trans(uint32_t& r0, uint32_t& r1,
                                                  uint32_t& r2, uint32_t& r3,
                                                  uint32_t addr) {
    asm volatile("ldmatrix.sync.aligned.m8n8.x4.trans.shared.b16 {%0,%1,%2,%3}, [%4];"
                 : "=r"(r0), "=r"(r1), "=r"(r2), "=r"(r3) : "r"(addr));
}

__device__ __forceinline__ void mma_f16(float& c0, float& c1, float& c2, float& c3,
                                        uint32_t a0, uint32_t a1, uint32_t a2, uint32_t a3,
                                        uint32_t b0, uint32_t b1) {
    asm volatile(
        "mma.sync.aligned.m16n8k16.row.col.f32.f16.f16.f32 "
        "{%0,%1,%2,%3}, {%4,%5,%6,%7}, {%8,%9}, {%0,%1,%2,%3};"
        : "+f"(c0), "+f"(c1), "+f"(c2), "+f"(c3)
        : "r"(a0), "r"(a1), "r"(a2), "r"(a3), "r"(b0), "r"(b1));
}

// ---------------- device scratch (no allocs allowed) ----------------
__device__ __half g_xh[DIM_B * DIM_N * DIM_D];         // 4 MB, fp16 x
__device__ __half g_wh[DIM_V * DIM_D * DIM_O];         // 4 MB, fp16 W (native [v][d][o])
__device__ float  g_cbias[DIM_B * DIM_F * DIM_O];      // bias @ W, full fp32

static constexpr int X_ELEMS = DIM_B * DIM_N * DIM_D;  // 2M
static constexpr int W_ELEMS = DIM_V * DIM_D * DIM_O;  // 2M
static constexpr int PREP_T = 512;
static constexpr int BIASBLK = DIM_B * DIM_F;          // 64, scheduled FIRST
static constexpr int XBLK = X_ELEMS / (PREP_T * 8);    // 512
static constexpr int WBLK = W_ELEMS / (PREP_T * 8);    // 512 (8 blocks per v)

// ---------------- fused prep: bias FIRST (long chains overlap convert wave) --
__global__ void __launch_bounds__(PREP_T) prep_kernel(
    const float* __restrict__ x,
    const int* __restrict__ idx,
    const float* __restrict__ bias_tab,
    const float* __restrict__ w_tab)
{
    const int bid = blockIdx.x;
    const int tid = threadIdx.x;

    if (bid < BIASBLK) {
        // ---- bias: cbias[p][o] = sum_d bias[v][d] * W[v][d][o], fp32
        // 8 slices x 64 d each -> 64-iteration critical path
        int p = bid;                    // 0..63
        int v = idx[p];
        int o = tid & 63;
        int slice = tid >> 6;           // 0..7
        const float* bptr = bias_tab + (size_t)v * DIM_D;
        const float* wptr = w_tab + (size_t)v * DIM_D * DIM_O + o;
        float acc = 0.f;
        int d0 = slice * 64;
        #pragma unroll 8
        for (int d = d0; d < d0 + 64; ++d)
            acc += bptr[d] * wptr[(size_t)d * DIM_O];
        __shared__ float red[PREP_T];
        red[tid] = acc;
        __syncthreads();
        if (slice == 0) {
            float s = 0.f;
            #pragma unroll
            for (int i = 0; i < 8; ++i) s += red[o + i * 64];
            g_cbias[p * DIM_O + o] = s;
        }
    } else {
        const float* src;
        __half* dst;
        size_t i;
        if (bid < BIASBLK + XBLK) {
            i = ((size_t)(bid - BIASBLK) * PREP_T + tid) * 8;
            src = x; dst = g_xh;
        } else {
            // 8 blocks per vocab entry; skip entries not referenced by idx
            int wb = bid - BIASBLK - XBLK;
            int v = wb >> 3;
            int used = __syncthreads_or(tid < DIM_B * DIM_F && idx[tid] == v);
            if (!used) return;
            i = ((size_t)wb * PREP_T + tid) * 8;
            src = w_tab; dst = g_wh;
        }
        float4 v0 = *reinterpret_cast<const float4*>(src + i);
        float4 v1 = *reinterpret_cast<const float4*>(src + i + 4);
        __half2 h[4];
        h[0] = __float22half2_rn(make_float2(v0.x, v0.y));
        h[1] = __float22half2_rn(make_float2(v0.z, v0.w));
        h[2] = __float22half2_rn(make_float2(v1.x, v1.y));
        h[3] = __float22half2_rn(make_float2(v1.z, v1.w));
        *reinterpret_cast<uint4*>(dst + i) = *reinterpret_cast<uint4*>(h);
    }
}

// ---------------- main GEMM: EXACT R13 config (best measured: 20.128 us) -----
// CTA tile: M=256, N=128 (2 f's x 64 o), K=512 in chunks of KC=64 halves.
// 512 threads, 16 warps as 8(m) x 2(n): warp tile 32 x 64.
// Grid = 4 x 8 x 4 = 128 CTAs < 148 SMs -> one wave.
static constexpr int M_CTA = 256;
static constexpr int KC = 64;                    // halves per chunk (4 k16 steps)
static constexpr int CHUNKS = DIM_D / KC;        // 8
static constexpr int STAGES = 3;

// A smem: [256 m][KC halves] rows of 128 B data, stride 36 words (9 quads, odd)
// B smem: [KC k][128 n] rows of 256 B data, stride 68 words (17 quads, odd)
// odd quad strides => ldmatrix 8-row phases hit distinct 16B banks.
static constexpr int A_RS = 36;                           // words
static constexpr int B_RS = 68;                           // words
static constexpr int A_BYTES  = M_CTA * A_RS * 4;         // 36864
static constexpr int B_BYTES  = KC * B_RS * 4;            // 17408
static constexpr int STAGE_BYTES = A_BYTES + B_BYTES;     // 54272
static constexpr int SMEM_TOTAL  = STAGES * STAGE_BYTES;  // 162816

__global__ void __launch_bounds__(512, 1) mm_kernel(
    const int* __restrict__ idx,
    float* __restrict__ out)
{
    extern __shared__ char smem[];
    const uint32_t smem_base = smem_u32(smem);

    const int tid  = threadIdx.x;
    const int wid  = tid >> 5;
    const int lane = tid & 31;
    const int grp  = lane >> 2;         // 0..7
    const int tg   = lane & 3;          // 0..3

    const int mtile  = blockIdx.x;      // 0..3  (256 rows each)
    const int ntile  = blockIdx.y;      // 0..7
    const int b      = blockIdx.z;      // 0..3
    const int f_base = ntile * 2;

    const int v0 = idx[b * DIM_F + f_base];
    const int v1 = idx[b * DIM_F + f_base + 1];

    const __half* xbase = g_xh + ((size_t)b * DIM_N + (size_t)mtile * M_CTA) * DIM_D;
    const __half* w0 = g_wh + (size_t)v0 * DIM_D * DIM_O;   // [d][o]
    const __half* w1 = g_wh + (size_t)v1 * DIM_D * DIM_O;

    // per chunk: A = 256 rows x 128 B = 2048 segs (4/thread)
    //            B = 64 k-rows x 256 B = 1024 segs (2/thread)
    auto load_stage = [&](int stage, int k0) {
        uint32_t abase = smem_base + stage * STAGE_BYTES;
        uint32_t bbase = abase + A_BYTES;
        #pragma unroll
        for (int i = 0; i < 4; ++i) {
            int seg = tid + 512 * i;
            int row = seg >> 3, c8 = seg & 7;        // 8 x 16B per A row
            cp_async16(abase + (row * A_RS + c8 * 4) * 4,
                       xbase + (size_t)row * DIM_D + k0 + c8 * 8);
        }
        #pragma unroll
        for (int i = 0; i < 2; ++i) {
            int seg = tid + 512 * i;
            int k = seg >> 4, c16 = seg & 15;        // 16 x 16B per B k-row
            const __half* wsrc = ((c16 < 8) ? w0 : w1)
                                 + (size_t)(k0 + k) * DIM_O + (c16 & 7) * 8;
            cp_async16(bbase + (k * B_RS + c16 * 4) * 4, wsrc);
        }
    };

    const int warp_m = (wid >> 1) * 32;  // 0..224
    const int warp_n = (wid & 1) * 64;

    // A x4 (non-trans): rows warp_m+mt*16+(lane&15), k-halfword (lane>>4)*8
    const uint32_t a_off0 = ((warp_m + (lane & 15)) * A_RS + (lane >> 4) * 4) * 4;
    // B x4 trans: k-row (lane>>3 & 1)*8 + (lane&7); n-half ntp*16 + (lane>>4)*8
    const uint32_t b_off0 = ((((lane >> 3) & 1) * 8 + (lane & 7)) * B_RS) * 4
                            + (warp_n + (lane >> 4) * 8) * 2;

    float acc[2][8][4];
    #pragma unroll
    for (int mt = 0; mt < 2; ++mt)
        #pragma unroll
        for (int nt = 0; nt < 8; ++nt)
            #pragma unroll
            for (int c = 0; c < 4; ++c) acc[mt][nt][c] = 0.f;

    // ---- prologue: prefetch 2 chunks
    load_stage(0, 0);
    asm volatile("cp.async.commit_group;" ::: "memory");
    load_stage(1, KC);
    asm volatile("cp.async.commit_group;" ::: "memory");

    int cs = 0, ls = 2;                  // compute stage, load stage
    for (int chunk = 0; chunk < CHUNKS; ++chunk) {
        asm volatile("cp.async.wait_group 1;" ::: "memory");  // chunk landed
        __syncthreads();
        if (chunk + 2 < CHUNKS) load_stage(ls, (chunk + 2) * KC);
        asm volatile("cp.async.commit_group;" ::: "memory");  // empty at tail OK

        const uint32_t a_st = smem_base + cs * STAGE_BYTES;
        const uint32_t b_st = a_st + A_BYTES;

        #pragma unroll
        for (int s = 0; s < KC / 16; ++s) {
            // B first (feeds all MMAs), then per-mt A LDSM + its 8 MMAs
            uint32_t bfr[8][2];
            #pragma unroll
            for (int ntp = 0; ntp < 4; ++ntp)
                ldmatrix_x4_trans(bfr[2 * ntp][0], bfr[2 * ntp][1],
                                  bfr[2 * ntp + 1][0], bfr[2 * ntp + 1][1],
                                  b_st + b_off0 + ntp * 32 + s * 16 * B_RS * 4);
            #pragma unroll
            for (int mt = 0; mt < 2; ++mt) {
                uint32_t afr[4];
                ldmatrix_x4(afr[0], afr[1], afr[2], afr[3],
                            a_st + a_off0 + mt * 16 * A_RS * 4 + s * 32);
                #pragma unroll
                for (int nt = 0; nt < 8; ++nt)
                    mma_f16(acc[mt][nt][0], acc[mt][nt][1], acc[mt][nt][2], acc[mt][nt][3],
                            afr[0], afr[1], afr[2], afr[3],
                            bfr[nt][0], bfr[nt][1]);
            }
        }
        cs = (cs == 2) ? 0 : cs + 1;
        ls = (ls == 2) ? 0 : ls + 1;
    }

    // ---- epilogue: add cbias, store float2 (c0/c1 at cols 2*tg, rows grp/+8)
    const float* cbp = g_cbias + (b * DIM_F + f_base) * DIM_O;
    float2 cb[8];
    #pragma unroll
    for (int nt = 0; nt < 8; ++nt)
        cb[nt] = *reinterpret_cast<const float2*>(cbp + warp_n + nt * 8 + 2 * tg);

    #pragma unroll
    for (int mt = 0; mt < 2; ++mt) {
        #pragma unroll
        for (int r2 = 0; r2 < 2; ++r2) {
            int m_global = mtile * M_CTA + warp_m + mt * 16 + grp + r2 * 8;
            float* rowp = out + (((size_t)b * DIM_N + m_global) * DIM_F + f_base) * DIM_O;
            #pragma unroll
            for (int nt = 0; nt < 8; ++nt) {
                float2 ov;
                ov.x = acc[mt][nt][r2 * 2 + 0] + cb[nt].x;
                ov.y = acc[mt][nt][r2 * 2 + 1] + cb[nt].y;
                *reinterpret_cast<float2*>(rowp + warp_n + nt * 8 + 2 * tg) = ov;
            }
        }
    }
}

// ---------------- launch ----------------
extern "C" void kernel_launch(void* const* d_in, const int* in_sizes, int n_in,
                              void* d_out, int out_size) {
    const float* x        = (const float*)d_in[0];   // [4,1024,512] f32
    const int*   idx      = (const int*)d_in[1];     // [4,16] i32
    const float* bias_tab = (const float*)d_in[2];   // [64,512] f32
    const float* w_tab    = (const float*)d_in[3];   // [64, 512*64] f32
    float* out = (float*)d_out;                      // [4,1024,16,64] f32

    static bool attr_set = false;
    if (!attr_set) {
        cudaFuncSetAttribute(mm_kernel,
                             cudaFuncAttributeMaxDynamicSharedMemorySize, SMEM_TOTAL);
        attr_set = true;
    }

    prep_kernel<<<BIASBLK + XBLK + WBLK, PREP_T>>>(x, idx, bias_tab, w_tab);

    dim3 grid(DIM_N / M_CTA, DIM_N / 128, DIM_B);    // (4, 8, 4) = 128 CTAs
    mm_kernel<<<grid, 512, SMEM_TOTAL>>>(idx, out);
}